// round 1
// baseline (speedup 1.0000x reference)
#include <cuda_runtime.h>
#include <math.h>

// Problem constants
#define Tt   2048      // B*S tokens
#define Dm   1024      // model dim
#define NHh  16        // heads
#define HDd  64        // head dim
#define Ll   2         // layers
#define HIDh 2048      // MoE hidden
#define Ee   8         // experts
#define Ss   1024      // seq len
#define Vv   32000     // vocab

// ---------------- scratch (device globals: allocation-free) ----------------
__device__ float g_x[Tt * Dm];
__device__ float g_xn[Tt * Dm];
__device__ float g_q[Tt * Dm];
__device__ float g_k[Tt * Dm];
__device__ float g_v[Tt * Dm];
__device__ float g_ctx[Tt * Dm];
__device__ float g_gbuf[Tt * HIDh];
__device__ int   g_cnt[Ee];
__device__ int   g_toks[Ee * Tt];
__device__ float g_wgts[Ee * Tt];

// ---------------- embedding gather ----------------
__global__ void embed_kernel(const int* __restrict__ tokens,
                             const float* __restrict__ embed,
                             float* __restrict__ x) {
    int t = blockIdx.x;
    int tok = tokens[t];
    const float4* src = (const float4*)(embed + (size_t)tok * Dm);
    float4* dst = (float4*)(x + (size_t)t * Dm);
    for (int i = threadIdx.x; i < Dm / 4; i += blockDim.x) dst[i] = src[i];
}

// ---------------- rmsnorm ----------------
__global__ void rmsnorm_kernel(const float* __restrict__ x,
                               const float* __restrict__ w,
                               float* __restrict__ y) {
    int t = blockIdx.x;
    const float* xr = x + (size_t)t * Dm;
    float s = 0.f;
    for (int i = threadIdx.x; i < Dm; i += 256) { float v = xr[i]; s += v * v; }
    __shared__ float red[256];
    red[threadIdx.x] = s;
    __syncthreads();
    for (int off = 128; off > 0; off >>= 1) {
        if (threadIdx.x < off) red[threadIdx.x] += red[threadIdx.x + off];
        __syncthreads();
    }
    float scale = rsqrtf(red[0] / (float)Dm + 1e-6f);
    for (int i = threadIdx.x; i < Dm; i += 256)
        y[(size_t)t * Dm + i] = xr[i] * scale * w[i];
}

// ---------------- generic SGEMM: C[M,N] = A[M,K] @ B[K,N] (+res) ----------------
// BM=BN=64, BK=16, 16x16 threads, 4x4 per thread. M,N multiples of 64.
__global__ void sgemm_nn(const float* __restrict__ A, const float* __restrict__ B,
                         float* C, const float* res,
                         int M, int N, int K) {
    __shared__ float As[16][64];
    __shared__ float Bs[16][64];
    int row0 = blockIdx.y * 64, col0 = blockIdx.x * 64;
    int tx = threadIdx.x, ty = threadIdx.y;
    int tid = ty * 16 + tx;
    int am = tid >> 2, ak = (tid & 3) * 4;
    int bk = tid >> 4, bn = (tid & 15) * 4;
    float acc[4][4] = {};
    for (int k0 = 0; k0 < K; k0 += 16) {
        float4 a4 = *(const float4*)(A + (size_t)(row0 + am) * K + k0 + ak);
        As[ak + 0][am] = a4.x; As[ak + 1][am] = a4.y;
        As[ak + 2][am] = a4.z; As[ak + 3][am] = a4.w;
        *(float4*)&Bs[bk][bn] = *(const float4*)(B + (size_t)(k0 + bk) * N + col0 + bn);
        __syncthreads();
#pragma unroll
        for (int kk = 0; kk < 16; kk++) {
            float a[4], b[4];
            *(float4*)a = *(float4*)&As[kk][ty * 4];
            *(float4*)b = *(float4*)&Bs[kk][tx * 4];
#pragma unroll
            for (int i = 0; i < 4; i++)
#pragma unroll
                for (int j = 0; j < 4; j++) acc[i][j] += a[i] * b[j];
        }
        __syncthreads();
    }
#pragma unroll
    for (int i = 0; i < 4; i++) {
        size_t r = row0 + ty * 4 + i;
#pragma unroll
        for (int j = 0; j < 4; j++) {
            size_t c = col0 + tx * 4 + j;
            float v = acc[i][j];
            if (res) v += res[r * N + c];
            C[r * N + c] = v;
        }
    }
}

// ---------------- SGEMM with transposed B: C[M,N] = A[M,K] @ B[N,K]^T ----------------
__global__ void sgemm_nt(const float* __restrict__ A, const float* __restrict__ B,
                         float* __restrict__ C, int M, int N, int K) {
    __shared__ float As[16][64];
    __shared__ float Bs[16][64];
    int row0 = blockIdx.y * 64, col0 = blockIdx.x * 64;
    int tx = threadIdx.x, ty = threadIdx.y;
    int tid = ty * 16 + tx;
    int am = tid >> 2, ak = (tid & 3) * 4;   // also reused for B (row-major [N,K])
    float acc[4][4] = {};
    for (int k0 = 0; k0 < K; k0 += 16) {
        float4 a4 = *(const float4*)(A + (size_t)(row0 + am) * K + k0 + ak);
        As[ak + 0][am] = a4.x; As[ak + 1][am] = a4.y;
        As[ak + 2][am] = a4.z; As[ak + 3][am] = a4.w;
        float4 b4 = *(const float4*)(B + (size_t)(col0 + am) * K + k0 + ak);
        Bs[ak + 0][am] = b4.x; Bs[ak + 1][am] = b4.y;
        Bs[ak + 2][am] = b4.z; Bs[ak + 3][am] = b4.w;
        __syncthreads();
#pragma unroll
        for (int kk = 0; kk < 16; kk++) {
            float a[4], b[4];
            *(float4*)a = *(float4*)&As[kk][ty * 4];
            *(float4*)b = *(float4*)&Bs[kk][tx * 4];
#pragma unroll
            for (int i = 0; i < 4; i++)
#pragma unroll
                for (int j = 0; j < 4; j++) acc[i][j] += a[i] * b[j];
        }
        __syncthreads();
    }
#pragma unroll
    for (int i = 0; i < 4; i++) {
        size_t r = row0 + ty * 4 + i;
#pragma unroll
        for (int j = 0; j < 4; j++) {
            size_t c = col0 + tx * 4 + j;
            C[r * N + c] = acc[i][j];
        }
    }
}

// ---------------- rope (in-place on q or k) ----------------
__global__ void rope_kernel(float* x) {
    int idx = blockIdx.x * 256 + threadIdx.x;
    if (idx >= Tt * NHh * 32) return;
    int d = idx & 31;
    int h = (idx >> 5) & 15;
    int t = idx >> 9;
    int s = t & (Ss - 1);
    double inv = pow(10000.0, -(double)d / 32.0);
    double ang = (double)s * inv;
    float c = (float)cos(ang), sn = (float)sin(ang);
    float* p = x + (size_t)t * Dm + h * HDd + d;
    float x1 = p[0], x2 = p[32];
    p[0]  = x1 * c  - x2 * sn;
    p[32] = x1 * sn + x2 * c;
}

// ---------------- flash attention (fp32, causal, 64x64 tiles) ----------------
__global__ void flash_attn_kernel(const float* __restrict__ Q,
                                  const float* __restrict__ Km,
                                  const float* __restrict__ Vm,
                                  float* __restrict__ O) {
    extern __shared__ float sm[];
    float* Qs    = sm;                 // 64*65
    float* Ks    = Qs + 64 * 65;       // 64*65
    float* Vs    = Ks + 64 * 65;       // 64*64
    float* Ps    = Vs + 64 * 64;       // 64*65
    float* row_m = Ps + 64 * 65;       // 64
    float* row_l = row_m + 64;         // 64
    float* resc  = row_l + 64;         // 64

    int qt = blockIdx.x;               // q tile 0..15
    int bh = blockIdx.y;               // 0..31
    int b = bh >> 4, h = bh & 15;
    int tx = threadIdx.x, ty = threadIdx.y;
    int tid = ty * 16 + tx;

    size_t base = (size_t)b * Ss * Dm + (size_t)h * HDd;

    // load Q tile
    {
        int r = tid >> 2;
        int c4 = (tid & 3) * 16;
        const float* src = Q + base + (size_t)(qt * 64 + r) * Dm + c4;
#pragma unroll
        for (int i = 0; i < 4; i++) {
            float4 vq = *(const float4*)(src + i * 4);
            Qs[r * 65 + c4 + i * 4 + 0] = vq.x;
            Qs[r * 65 + c4 + i * 4 + 1] = vq.y;
            Qs[r * 65 + c4 + i * 4 + 2] = vq.z;
            Qs[r * 65 + c4 + i * 4 + 3] = vq.w;
        }
    }
    if (tid < 64) { row_m[tid] = -1e30f; row_l[tid] = 0.f; }

    float acc[4][4] = {};
    __syncthreads();

    for (int jt = 0; jt <= qt; jt++) {
        // load K and V tiles
        {
            int r = tid >> 2;
            int c4 = (tid & 3) * 16;
            const float* ksrc = Km + base + (size_t)(jt * 64 + r) * Dm + c4;
            const float* vsrc = Vm + base + (size_t)(jt * 64 + r) * Dm + c4;
#pragma unroll
            for (int i = 0; i < 4; i++) {
                float4 vk = *(const float4*)(ksrc + i * 4);
                Ks[r * 65 + c4 + i * 4 + 0] = vk.x;
                Ks[r * 65 + c4 + i * 4 + 1] = vk.y;
                Ks[r * 65 + c4 + i * 4 + 2] = vk.z;
                Ks[r * 65 + c4 + i * 4 + 3] = vk.w;
                float4 vv = *(const float4*)(vsrc + i * 4);
                *(float4*)&Vs[r * 64 + c4 + i * 4] = vv;
            }
        }
        __syncthreads();

        // P = Q K^T * 0.125 (+causal mask on diagonal tile)
        float p[4][4] = {};
#pragma unroll 4
        for (int d = 0; d < 64; d++) {
            float a[4], bv[4];
#pragma unroll
            for (int i = 0; i < 4; i++) a[i]  = Qs[(ty * 4 + i) * 65 + d];
#pragma unroll
            for (int j = 0; j < 4; j++) bv[j] = Ks[(tx * 4 + j) * 65 + d];
#pragma unroll
            for (int i = 0; i < 4; i++)
#pragma unroll
                for (int j = 0; j < 4; j++) p[i][j] += a[i] * bv[j];
        }
#pragma unroll
        for (int i = 0; i < 4; i++) {
            int gq = qt * 64 + ty * 4 + i;
#pragma unroll
            for (int j = 0; j < 4; j++) {
                int gk = jt * 64 + tx * 4 + j;
                float pv = p[i][j] * 0.125f;
                if (jt == qt && gk > gq) pv = -1e30f;
                Ps[(ty * 4 + i) * 65 + tx * 4 + j] = pv;
            }
        }
        __syncthreads();

        // online softmax row pass
        if (tid < 64) {
            int r = tid;
            float mx = row_m[r];
            float tmax = -1e30f;
            for (int c = 0; c < 64; c++) tmax = fmaxf(tmax, Ps[r * 65 + c]);
            float nm = fmaxf(mx, tmax);
            float sum = 0.f;
            for (int c = 0; c < 64; c++) {
                float e = expf(Ps[r * 65 + c] - nm);
                Ps[r * 65 + c] = e;
                sum += e;
            }
            float rf = expf(mx - nm);
            row_l[r] = row_l[r] * rf + sum;
            row_m[r] = nm;
            resc[r] = rf;
        }
        __syncthreads();

        // O = O*rescale + P @ V
        float rs[4];
#pragma unroll
        for (int i = 0; i < 4; i++) rs[i] = resc[ty * 4 + i];
#pragma unroll
        for (int i = 0; i < 4; i++)
#pragma unroll
            for (int j = 0; j < 4; j++) acc[i][j] *= rs[i];
#pragma unroll 4
        for (int c = 0; c < 64; c++) {
            float pv[4], vv[4];
#pragma unroll
            for (int i = 0; i < 4; i++) pv[i] = Ps[(ty * 4 + i) * 65 + c];
#pragma unroll
            for (int j = 0; j < 4; j++) vv[j] = Vs[c * 64 + tx * 4 + j];
#pragma unroll
            for (int i = 0; i < 4; i++)
#pragma unroll
                for (int j = 0; j < 4; j++) acc[i][j] += pv[i] * vv[j];
        }
        __syncthreads();
    }

    float inv_l[4];
#pragma unroll
    for (int i = 0; i < 4; i++) inv_l[i] = 1.0f / row_l[ty * 4 + i];
#pragma unroll
    for (int i = 0; i < 4; i++) {
        size_t r = qt * 64 + ty * 4 + i;
#pragma unroll
        for (int j = 0; j < 4; j++)
            O[base + r * Dm + tx * 4 + j] = acc[i][j] * inv_l[i];
    }
}

// ---------------- router: top-2 + softmax gates + expert lists ----------------
__global__ void zero_cnt_kernel(int* cnt) {
    if (threadIdx.x < Ee) cnt[threadIdx.x] = 0;
}

__global__ void router_kernel(const float* __restrict__ xn,
                              const float* __restrict__ rw,
                              int* cnt, int* toks, float* wgts) {
    int t = blockIdx.x;
    int lane = threadIdx.x;          // 64 threads
    int e = lane >> 3, sub = lane & 7;
    const float* xr = xn + (size_t)t * Dm;
    const float* wr = rw + (size_t)e * Dm;
    float s = 0.f;
    for (int i = sub; i < Dm; i += 8) s += xr[i] * wr[i];
    for (int off = 4; off > 0; off >>= 1) s += __shfl_down_sync(0xffffffffu, s, off, 8);
    __shared__ float lg[Ee];
    if (sub == 0) lg[e] = s;
    __syncthreads();
    if (threadIdx.x == 0) {
        int i0 = 0; float v0 = lg[0];
        for (int k = 1; k < Ee; k++) if (lg[k] > v0) { v0 = lg[k]; i0 = k; }
        int i1 = -1; float v1 = -1e30f;
        for (int k = 0; k < Ee; k++) {
            if (k == i0) continue;
            if (lg[k] > v1) { v1 = lg[k]; i1 = k; }
        }
        float e1 = expf(v1 - v0);
        float sum = 1.0f + e1;
        float w0 = 1.0f / sum, w1 = e1 / sum;
        int p0 = atomicAdd(&cnt[i0], 1);
        toks[i0 * Tt + p0] = t; wgts[i0 * Tt + p0] = w0;
        int p1 = atomicAdd(&cnt[i1], 1);
        toks[i1 * Tt + p1] = t; wgts[i1 * Tt + p1] = w1;
    }
}

// ---------------- MoE up: G = silu(Xg@W1) * (Xg@W3), gathered rows ----------------
__global__ void moe_up_kernel(const float* __restrict__ X, const int* __restrict__ toks,
                              const int* __restrict__ cntp,
                              const float* __restrict__ W1, const float* __restrict__ W3,
                              float* __restrict__ G) {
    int Me = *cntp;
    int row0 = blockIdx.y * 64;
    if (row0 >= Me) return;
    int col0 = blockIdx.x * 64;
    __shared__ float As[16][64];
    __shared__ float B1s[16][64];
    __shared__ float B3s[16][64];
    int tx = threadIdx.x, ty = threadIdx.y;
    int tid = ty * 16 + tx;
    int am = tid >> 2, ak = (tid & 3) * 4;
    int bk = tid >> 4, bn = (tid & 15) * 4;
    int m = row0 + am;
    int tsrc = toks[m < Me ? m : (Me - 1)];
    float acc1[4][4] = {}, acc3[4][4] = {};
    for (int k0 = 0; k0 < Dm; k0 += 16) {
        float4 a4 = *(const float4*)(X + (size_t)tsrc * Dm + k0 + ak);
        As[ak + 0][am] = a4.x; As[ak + 1][am] = a4.y;
        As[ak + 2][am] = a4.z; As[ak + 3][am] = a4.w;
        *(float4*)&B1s[bk][bn] = *(const float4*)(W1 + (size_t)(k0 + bk) * HIDh + col0 + bn);
        *(float4*)&B3s[bk][bn] = *(const float4*)(W3 + (size_t)(k0 + bk) * HIDh + col0 + bn);
        __syncthreads();
#pragma unroll
        for (int kk = 0; kk < 16; kk++) {
            float a[4], b1[4], b3[4];
            *(float4*)a  = *(float4*)&As[kk][ty * 4];
            *(float4*)b1 = *(float4*)&B1s[kk][tx * 4];
            *(float4*)b3 = *(float4*)&B3s[kk][tx * 4];
#pragma unroll
            for (int i = 0; i < 4; i++)
#pragma unroll
                for (int j = 0; j < 4; j++) {
                    acc1[i][j] += a[i] * b1[j];
                    acc3[i][j] += a[i] * b3[j];
                }
        }
        __syncthreads();
    }
#pragma unroll
    for (int i = 0; i < 4; i++) {
        int r = row0 + ty * 4 + i;
        if (r < Me) {
#pragma unroll
            for (int j = 0; j < 4; j++) {
                int c = col0 + tx * 4 + j;
                float h1 = acc1[i][j];
                float sil = h1 / (1.0f + expf(-h1));
                G[(size_t)r * HIDh + c] = sil * acc3[i][j];
            }
        }
    }
}

// ---------------- MoE down: X[tok[i]] += wgt[i] * (G @ W2) ----------------
__global__ void moe_down_kernel(const float* __restrict__ G, const float* __restrict__ W2,
                                const int* __restrict__ toks, const float* __restrict__ wgt,
                                const int* __restrict__ cntp, float* X) {
    int Me = *cntp;
    int row0 = blockIdx.y * 64;
    if (row0 >= Me) return;
    int col0 = blockIdx.x * 64;
    __shared__ float As[16][64];
    __shared__ float Bs[16][64];
    int tx = threadIdx.x, ty = threadIdx.y;
    int tid = ty * 16 + tx;
    int am = tid >> 2, ak = (tid & 3) * 4;
    int bk = tid >> 4, bn = (tid & 15) * 4;
    int m = row0 + am;
    int mr = m < Me ? m : (Me - 1);
    float acc[4][4] = {};
    for (int k0 = 0; k0 < HIDh; k0 += 16) {
        float4 a4 = *(const float4*)(G + (size_t)mr * HIDh + k0 + ak);
        As[ak + 0][am] = a4.x; As[ak + 1][am] = a4.y;
        As[ak + 2][am] = a4.z; As[ak + 3][am] = a4.w;
        *(float4*)&Bs[bk][bn] = *(const float4*)(W2 + (size_t)(k0 + bk) * Dm + col0 + bn);
        __syncthreads();
#pragma unroll
        for (int kk = 0; kk < 16; kk++) {
            float a[4], b[4];
            *(float4*)a = *(float4*)&As[kk][ty * 4];
            *(float4*)b = *(float4*)&Bs[kk][tx * 4];
#pragma unroll
            for (int i = 0; i < 4; i++)
#pragma unroll
                for (int j = 0; j < 4; j++) acc[i][j] += a[i] * b[j];
        }
        __syncthreads();
    }
#pragma unroll
    for (int i = 0; i < 4; i++) {
        int r = row0 + ty * 4 + i;
        if (r < Me) {
            int t = toks[r];
            float w = wgt[r];
#pragma unroll
            for (int j = 0; j < 4; j++) {
                int c = col0 + tx * 4 + j;
                X[(size_t)t * Dm + c] += w * acc[i][j];
            }
        }
    }
}

// ---------------- launcher ----------------
extern "C" void kernel_launch(void* const* d_in, const int* in_sizes, int n_in,
                              void* d_out, int out_size) {
    (void)in_sizes; (void)n_in; (void)out_size;
    const int*   tokens       = (const int*)d_in[0];
    const float* embed        = (const float*)d_in[1];
    const float* attn_norm_w  = (const float*)d_in[2];
    const float* wq           = (const float*)d_in[3];
    const float* wk           = (const float*)d_in[4];
    const float* wv           = (const float*)d_in[5];
    const float* wo           = (const float*)d_in[6];
    const float* moe_norm_w   = (const float*)d_in[7];
    const float* router_w     = (const float*)d_in[8];
    const float* w1           = (const float*)d_in[9];
    const float* w2           = (const float*)d_in[10];
    const float* w3           = (const float*)d_in[11];
    const float* final_norm_w = (const float*)d_in[12];
    float* out = (float*)d_out;

    float *x, *xn, *q, *k, *v, *ctx, *gbuf, *wgts;
    int *cnt, *toks;
    cudaGetSymbolAddress((void**)&x,    g_x);
    cudaGetSymbolAddress((void**)&xn,   g_xn);
    cudaGetSymbolAddress((void**)&q,    g_q);
    cudaGetSymbolAddress((void**)&k,    g_k);
    cudaGetSymbolAddress((void**)&v,    g_v);
    cudaGetSymbolAddress((void**)&ctx,  g_ctx);
    cudaGetSymbolAddress((void**)&gbuf, g_gbuf);
    cudaGetSymbolAddress((void**)&cnt,  g_cnt);
    cudaGetSymbolAddress((void**)&toks, g_toks);
    cudaGetSymbolAddress((void**)&wgts, g_wgts);

    const int FLASH_SMEM = (3 * 64 * 65 + 64 * 64 + 3 * 64) * 4;
    cudaFuncSetAttribute(flash_attn_kernel,
                         cudaFuncAttributeMaxDynamicSharedMemorySize, FLASH_SMEM);

    dim3 b1(16, 16);

    embed_kernel<<<Tt, 256>>>(tokens, embed, x);

    for (int l = 0; l < Ll; l++) {
        rmsnorm_kernel<<<Tt, 256>>>(x, attn_norm_w + (size_t)l * Dm, xn);

        dim3 g1(Dm / 64, Tt / 64);
        sgemm_nn<<<g1, b1>>>(xn, wq + (size_t)l * Dm * Dm, q, nullptr, Tt, Dm, Dm);
        sgemm_nn<<<g1, b1>>>(xn, wk + (size_t)l * Dm * Dm, k, nullptr, Tt, Dm, Dm);
        sgemm_nn<<<g1, b1>>>(xn, wv + (size_t)l * Dm * Dm, v, nullptr, Tt, Dm, Dm);

        int nrope = Tt * NHh * 32;
        rope_kernel<<<(nrope + 255) / 256, 256>>>(q);
        rope_kernel<<<(nrope + 255) / 256, 256>>>(k);

        flash_attn_kernel<<<dim3(Ss / 64, 2 * NHh), b1, FLASH_SMEM>>>(q, k, v, ctx);

        // x = x + ctx @ wo
        sgemm_nn<<<g1, b1>>>(ctx, wo + (size_t)l * Dm * Dm, x, x, Tt, Dm, Dm);

        rmsnorm_kernel<<<Tt, 256>>>(x, moe_norm_w + (size_t)l * Dm, xn);

        zero_cnt_kernel<<<1, 32>>>(cnt);
        router_kernel<<<Tt, 64>>>(xn, router_w + (size_t)l * Ee * Dm, cnt, toks, wgts);

        for (int e = 0; e < Ee; e++) {
            moe_up_kernel<<<dim3(HIDh / 64, Tt / 64), b1>>>(
                xn, toks + e * Tt, cnt + e,
                w1 + ((size_t)l * Ee + e) * Dm * HIDh,
                w3 + ((size_t)l * Ee + e) * Dm * HIDh, gbuf);
            moe_down_kernel<<<dim3(Dm / 64, Tt / 64), b1>>>(
                gbuf, w2 + ((size_t)l * Ee + e) * HIDh * Dm,
                toks + e * Tt, wgts + e * Tt, cnt + e, x);
        }
    }

    rmsnorm_kernel<<<Tt, 256>>>(x, final_norm_w, xn);
    sgemm_nt<<<dim3(Vv / 64, Tt / 64), b1>>>(xn, embed, out, Tt, Vv, Dm);
}